// round 7
// baseline (speedup 1.0000x reference)
#include <cuda_runtime.h>
#include <cstdint>

#define MAX_SEG  131072
#define MAX_ROWS 4505600

// Scratch (no allocs allowed -> __device__ globals)
__device__ unsigned g_counts[MAX_SEG];    // all-rows per-segment counts
__device__ float    g_inv[MAX_SEG];       // 1 / max(count, 1)
__device__ unsigned g_countsB[MAX_SEG];   // portion-B (gather) counts
__device__ unsigned g_offs_tmp[MAX_SEG];
__device__ unsigned g_blk_sums[256];
__device__ unsigned g_blk_off[256];
__device__ unsigned g_offsets[MAX_SEG];
__device__ unsigned g_cursor[MAX_SEG];
__device__ int      g_rowsB[MAX_ROWS];    // portion-B row ids grouped by segment

// ---------------------------------------------------------------------------
// 1: zero output + both count arrays
// ---------------------------------------------------------------------------
__global__ void zero_kernel(float4* __restrict__ out4, int n4, int n_seg) {
    int i = blockIdx.x * blockDim.x + threadIdx.x;
    if (i < n4) out4[i] = make_float4(0.f, 0.f, 0.f, 0.f);
    if (i < n_seg) { g_counts[i] = 0u; g_countsB[i] = 0u; }
}

// ---------------------------------------------------------------------------
// 2: histogram (all rows -> g_counts; rows >= A also -> g_countsB)
// ---------------------------------------------------------------------------
__global__ void hist_kernel(const int* __restrict__ index, int n_rows, int A) {
    int i = blockIdx.x * blockDim.x + threadIdx.x;
    if (i < n_rows) {
        int s = index[i];
        atomicAdd(&g_counts[s], 1u);
        if (i >= A) atomicAdd(&g_countsB[s], 1u);
    }
}

// ---------------------------------------------------------------------------
// 3: per-block exclusive scan of g_countsB (1024 per block)
// ---------------------------------------------------------------------------
__global__ void scan_blocks(int n_seg) {
    __shared__ unsigned s[256];
    int b = blockIdx.x, t = threadIdx.x;
    int base = b * 1024 + t * 4;
    unsigned v0 = 0, v1 = 0, v2 = 0, v3 = 0;
    if (base + 0 < n_seg) v0 = g_countsB[base + 0];
    if (base + 1 < n_seg) v1 = g_countsB[base + 1];
    if (base + 2 < n_seg) v2 = g_countsB[base + 2];
    if (base + 3 < n_seg) v3 = g_countsB[base + 3];
    unsigned tsum = v0 + v1 + v2 + v3;
    s[t] = tsum;
    __syncthreads();
    for (int d = 1; d < 256; d <<= 1) {
        unsigned add = (t >= d) ? s[t - d] : 0u;
        __syncthreads();
        s[t] += add;
        __syncthreads();
    }
    unsigned excl = s[t] - tsum;
    if (base + 0 < n_seg) g_offs_tmp[base + 0] = excl;
    if (base + 1 < n_seg) g_offs_tmp[base + 1] = excl + v0;
    if (base + 2 < n_seg) g_offs_tmp[base + 2] = excl + v0 + v1;
    if (base + 3 < n_seg) g_offs_tmp[base + 3] = excl + v0 + v1 + v2;
    if (t == 255) g_blk_sums[b] = s[255];
}

// ---------------------------------------------------------------------------
// 4: scan block totals (single block)
// ---------------------------------------------------------------------------
__global__ void scan_top(int nblk) {
    __shared__ unsigned s[256];
    int t = threadIdx.x;
    unsigned v = (t < nblk) ? g_blk_sums[t] : 0u;
    s[t] = v;
    __syncthreads();
    for (int d = 1; d < 256; d <<= 1) {
        unsigned add = (t >= d) ? s[t - d] : 0u;
        __syncthreads();
        s[t] += add;
        __syncthreads();
    }
    if (t < nblk) g_blk_off[t] = s[t] - v;
}

// ---------------------------------------------------------------------------
// 5: final offsets + cursors + inverse counts
// ---------------------------------------------------------------------------
__global__ void finalize_offsets(int n_seg) {
    int i = blockIdx.x * blockDim.x + threadIdx.x;
    if (i < n_seg) {
        unsigned o = g_offs_tmp[i] + g_blk_off[i >> 10];
        g_offsets[i] = o;
        g_cursor[i]  = o;
        g_inv[i] = 1.0f / fmaxf((float)g_counts[i], 1.0f);
    }
}

// ---------------------------------------------------------------------------
// 6: place portion-B row ids into segment-grouped list
// ---------------------------------------------------------------------------
__global__ void build_rows(const int* __restrict__ index, int n_rows, int A) {
    int i = A + blockIdx.x * blockDim.x + threadIdx.x;
    if (i < n_rows) {
        int s = index[i];
        unsigned p = atomicAdd(&g_cursor[s], 1u);
        g_rowsB[p] = i;
    }
}

// ---------------------------------------------------------------------------
// 7: fused hybrid. Every k-th block is a gather block (8 segments, warp each),
//    the rest are atomic-scatter blocks (16 rows each, 16 threads/row).
//    Both paths pre-scale by 1/count so no finalize pass is needed.
// ---------------------------------------------------------------------------
__global__ void fused_kernel(const float4* __restrict__ x4,
                             const int* __restrict__ index,
                             float* __restrict__ out,
                             int A, int n_seg, int k, int n_gb) {
    int b = blockIdx.x;
    int t = threadIdx.x;

    if ((b % k) == 0 && (b / k) < n_gb) {
        // ---- gather role: warp per segment, lane = float2 column ----
        int seg  = (b / k) * 8 + (t >> 5);
        int lane = t & 31;
        if (seg >= n_seg) return;
        unsigned cnt = g_countsB[seg];
        if (cnt == 0) return;
        unsigned start = g_offsets[seg];
        const float2* x2 = (const float2*)x4;

        float2 a0 = {0.f,0.f}, a1 = {0.f,0.f}, a2 = {0.f,0.f}, a3 = {0.f,0.f};
        unsigned r = 0;
        for (; r + 4 <= cnt; r += 4) {
            int i0 = g_rowsB[start + r + 0];
            int i1 = g_rowsB[start + r + 1];
            int i2 = g_rowsB[start + r + 2];
            int i3 = g_rowsB[start + r + 3];
            float2 v0 = x2[(size_t)i0 * 32 + lane];
            float2 v1 = x2[(size_t)i1 * 32 + lane];
            float2 v2 = x2[(size_t)i2 * 32 + lane];
            float2 v3 = x2[(size_t)i3 * 32 + lane];
            a0.x += v0.x; a0.y += v0.y;
            a1.x += v1.x; a1.y += v1.y;
            a2.x += v2.x; a2.y += v2.y;
            a3.x += v3.x; a3.y += v3.y;
        }
        for (; r < cnt; r++) {
            int i0 = g_rowsB[start + r];
            float2 v = x2[(size_t)i0 * 32 + lane];
            a0.x += v.x; a0.y += v.y;
        }
        float inv = g_inv[seg];
        float rx = (a0.x + a1.x + a2.x + a3.x) * inv;
        float ry = (a0.y + a1.y + a2.y + a3.y) * inv;
        float* dst = out + (size_t)seg * 64 + lane * 2;
        asm volatile("red.global.add.v2.f32 [%0], {%1, %2};"
                     :: "l"(dst), "f"(rx), "f"(ry) : "memory");
    } else {
        // ---- atomic role: rows [0, A), 16 rows per block ----
        int ngb_before = (b + k - 1) / k;
        if (ngb_before > n_gb) ngb_before = n_gb;
        int ab   = b - ngb_before;
        int row  = ab * 16 + (t >> 4);
        int lane = t & 15;
        if (row >= A) return;

        int seg = index[row];              // 16 lanes broadcast
        float inv = g_inv[seg];
        float4 v = x4[(size_t)row * 16 + lane];
        v.x *= inv; v.y *= inv; v.z *= inv; v.w *= inv;

        float* dst = out + (size_t)seg * 64 + lane * 4;
        asm volatile("red.global.add.v4.f32 [%0], {%1, %2, %3, %4};"
                     :: "l"(dst), "f"(v.x), "f"(v.y), "f"(v.z), "f"(v.w)
                     : "memory");
    }
}

// ---------------------------------------------------------------------------
extern "C" void kernel_launch(void* const* d_in, const int* in_sizes, int n_in,
                              void* d_out, int out_size) {
    const float4* x4    = (const float4*)d_in[0];
    const int*    index = (const int*)d_in[1];
    float*        out   = (float*)d_out;

    int n_rows = in_sizes[1];
    int n_seg  = out_size / 64;
    int n4     = out_size / 4;

    // Split point: fraction f=0.53 of rows via atomic path (LTS), rest gather (DRAM).
    int A = (int)((long long)n_rows * 53 / 100);

    int T = 256;
    int seg_blocks = (n_seg + T - 1) / T;
    int row_blocks = (n_rows + T - 1) / T;
    int nblk_scan  = (n_seg + 1023) / 1024;
    int nB         = n_rows - A;
    int rowB_blocks = (nB + T - 1) / T;

    {
        int n = (n4 > n_seg) ? n4 : n_seg;
        zero_kernel<<<(n + T - 1) / T, T>>>((float4*)d_out, n4, n_seg);
    }
    hist_kernel<<<row_blocks, T>>>(index, n_rows, A);
    scan_blocks<<<nblk_scan, 256>>>(n_seg);
    scan_top<<<1, 256>>>(nblk_scan);
    finalize_offsets<<<seg_blocks, T>>>(n_seg);
    if (rowB_blocks > 0)
        build_rows<<<rowB_blocks, T>>>(index, n_rows, A);

    int n_atomic_blocks = (A + 15) / 16;
    int n_gb            = (n_seg + 7) / 8;
    int total_blocks    = n_atomic_blocks + n_gb;
    int k = total_blocks / n_gb;
    if (k < 1) k = 1;
    fused_kernel<<<total_blocks, T>>>(x4, index, out, A, n_seg, k, n_gb);
}

// round 8
// speedup vs baseline: 1.1703x; 1.1703x over previous
#include <cuda_runtime.h>
#include <cstdint>

// Scratch: per-segment counts (num_segments = out_size/64 <= 131072 assumed).
__device__ float g_counts[131072];

// ---------------------------------------------------------------------------
// Scatter-add. 16 threads cooperate on one row (64 floats = 16 x float4).
// Each thread: one streaming (evict-first) float4 load of x, one
// red.global.add.v4.f32 into the L2-resident segment accumulator.
// Group-leader adds 1.0 to the segment count.
// ---------------------------------------------------------------------------
__global__ void __launch_bounds__(256) scatter_kernel(
        const float4* __restrict__ x4,
        const int* __restrict__ index,     // int32 (JAX x64 disabled)
        float* __restrict__ out,
        int n_rows) {
    int gid = blockIdx.x * blockDim.x + threadIdx.x;
    int row  = gid >> 4;
    int lane = gid & 15;
    if (row >= n_rows) return;

    // All 16 lanes load the same address -> single sector, HW broadcast.
    // Streaming hint: never reused.
    int seg = __ldcs(index + row);

    float4 v = __ldcs(x4 + (size_t)row * 16 + lane);

    float* dst = out + (size_t)seg * 64 + lane * 4;
    asm volatile("red.global.add.v4.f32 [%0], {%1, %2, %3, %4};"
                 :: "l"(dst), "f"(v.x), "f"(v.y), "f"(v.z), "f"(v.w)
                 : "memory");

    if (lane == 0) {
        float* cptr = &g_counts[seg];
        asm volatile("red.global.add.f32 [%0], %1;"
                     :: "l"(cptr), "f"(1.0f)
                     : "memory");
    }
}

// ---------------------------------------------------------------------------
// Divide each segment row by max(count, 1). L2-hot.
// ---------------------------------------------------------------------------
__global__ void __launch_bounds__(256) finalize_kernel(float4* __restrict__ out4,
                                                       int n_seg) {
    int i = blockIdx.x * blockDim.x + threadIdx.x;   // one float4 per thread
    int total = n_seg * 16;                          // 16 float4 per segment
    if (i >= total) return;
    float c = g_counts[i >> 4];
    float inv = 1.0f / fmaxf(c, 1.0f);
    float4 v = out4[i];
    v.x *= inv; v.y *= inv; v.z *= inv; v.w *= inv;
    out4[i] = v;
}

// ---------------------------------------------------------------------------
extern "C" void kernel_launch(void* const* d_in, const int* in_sizes, int n_in,
                              void* d_out, int out_size) {
    const float4* x4    = (const float4*)d_in[0];
    const int*    index = (const int*)d_in[1];
    float*        out   = (float*)d_out;

    int n_rows = in_sizes[1];        // len(index) == N
    int n_seg  = out_size / 64;      // D = 64

    // Zero accumulators via memset nodes (faster than a kernel, fewer launches).
    cudaMemsetAsync(d_out, 0, (size_t)out_size * sizeof(float));
    void* counts_ptr = nullptr;
    cudaGetSymbolAddress(&counts_ptr, g_counts);
    cudaMemsetAsync(counts_ptr, 0, (size_t)n_seg * sizeof(float));

    {
        int T = 256;
        long long total = (long long)n_rows * 16;
        int blocks = (int)((total + T - 1) / T);
        scatter_kernel<<<blocks, T>>>(x4, index, out, n_rows);
    }
    {
        int T = 256;
        int total = n_seg * 16;
        int blocks = (total + T - 1) / T;
        finalize_kernel<<<blocks, T>>>((float4*)d_out, n_seg);
    }
}

// round 10
// speedup vs baseline: 1.1795x; 1.0079x over previous
#include <cuda_runtime.h>
#include <cstdint>

// Scratch: per-segment counts (num_segments = out_size/64 <= 131072 assumed).
__device__ float g_counts[131072];

// ---------------------------------------------------------------------------
// Scatter-add. 16 threads cooperate on one row (64 floats = 16 x float4).
// Each thread: one streaming float4 load of x, one red.global.add.v4.f32
// (128-bit = max red width on sm_103a) into the L2-resident accumulator.
// Group-leader adds 1.0 to the segment count.
// ---------------------------------------------------------------------------
__global__ void __launch_bounds__(256) scatter_kernel(
        const float4* __restrict__ x4,
        const int* __restrict__ index,     // int32 (JAX x64 disabled)
        float* __restrict__ out,
        int n_rows) {
    int gid = blockIdx.x * blockDim.x + threadIdx.x;
    int row  = gid >> 4;
    int lane = gid & 15;
    if (row >= n_rows) return;

    // All 16 lanes load the same address -> single sector, HW broadcast.
    int seg = __ldcs(index + row);

    float4 v = __ldcs(x4 + (size_t)row * 16 + lane);

    float* dst = out + (size_t)seg * 64 + lane * 4;
    asm volatile("red.global.add.v4.f32 [%0], {%1, %2, %3, %4};"
                 :: "l"(dst), "f"(v.x), "f"(v.y), "f"(v.z), "f"(v.w)
                 : "memory");

    if (lane == 0) {
        float* cptr = &g_counts[seg];
        asm volatile("red.global.add.f32 [%0], %1;"
                     :: "l"(cptr), "f"(1.0f)
                     : "memory");
    }
}

// ---------------------------------------------------------------------------
// Divide by max(count,1). 4 threads per segment, 4 float4 per thread (ILP=4).
// ---------------------------------------------------------------------------
__global__ void __launch_bounds__(256) finalize_kernel(float4* __restrict__ out4,
                                                       int n_seg) {
    int t = blockIdx.x * blockDim.x + threadIdx.x;
    int seg  = t >> 2;              // 4 threads per segment
    int quad = t & 3;               // each owns 4 consecutive float4
    if (seg >= n_seg) return;

    float c = g_counts[seg];        // broadcast across the 4 threads
    float inv = 1.0f / fmaxf(c, 1.0f);

    float4* p = out4 + (size_t)seg * 16 + quad * 4;
    float4 v0 = p[0];
    float4 v1 = p[1];
    float4 v2 = p[2];
    float4 v3 = p[3];
    v0.x *= inv; v0.y *= inv; v0.z *= inv; v0.w *= inv;
    v1.x *= inv; v1.y *= inv; v1.z *= inv; v1.w *= inv;
    v2.x *= inv; v2.y *= inv; v2.z *= inv; v2.w *= inv;
    v3.x *= inv; v3.y *= inv; v3.z *= inv; v3.w *= inv;
    p[0] = v0;
    p[1] = v1;
    p[2] = v2;
    p[3] = v3;
}

// ---------------------------------------------------------------------------
extern "C" void kernel_launch(void* const* d_in, const int* in_sizes, int n_in,
                              void* d_out, int out_size) {
    const float4* x4    = (const float4*)d_in[0];
    const int*    index = (const int*)d_in[1];
    float*        out   = (float*)d_out;

    int n_rows = in_sizes[1];        // len(index) == N
    int n_seg  = out_size / 64;      // D = 64

    // Zero accumulators via memset nodes.
    cudaMemsetAsync(d_out, 0, (size_t)out_size * sizeof(float));
    void* counts_ptr = nullptr;
    cudaGetSymbolAddress(&counts_ptr, g_counts);
    cudaMemsetAsync(counts_ptr, 0, (size_t)n_seg * sizeof(float));

    {
        int T = 256;
        long long total = (long long)n_rows * 16;
        int blocks = (int)((total + T - 1) / T);
        scatter_kernel<<<blocks, T>>>(x4, index, out, n_rows);
    }
    {
        int T = 256;
        long long total = (long long)n_seg * 4;
        int blocks = (int)((total + T - 1) / T);
        finalize_kernel<<<blocks, T>>>((float4*)d_out, n_seg);
    }
}